// round 1
// baseline (speedup 1.0000x reference)
#include <cuda_runtime.h>

#define NN    200
#define HH    20
#define TB    400
#define OUTD  64
#define HSLOT 64
#define HP    201
#define MAXZ  64
#define NTH   512

#define SMEM_FLOATS (HSLOT*HP + 4*NN + NTH)
#define SMEM_BYTES  (SMEM_FLOATS * 4)

// ---------------- device scratch (no allocations allowed) ----------------
__device__ float         g_tin[TB*HH*NN];   // input  transposed to (t,k,n)
__device__ float         g_tnz[TB*HH*NN];   // noise_in[...,0] transposed to (t,k,n)
__device__ float         g_wl [NN*NN];      // wl -> then w_n with D==0 entries zeroed
__device__ unsigned char g_dt [NN*NN];      // g_dt[i*NN+j] = delay D[j,i]  (0..49)
__device__ float         g_rowsum[NN];
__device__ float         g_invnorm;
__device__ float         g_lm1[OUTD*NN];
__device__ float         g_lmt[OUTD*NN];
__device__ float         g_csrw[NN*MAXZ];   // zero-delay weights per node
__device__ int           g_csrj[NN*MAXZ];   // zero-delay neighbor indices
__device__ int           g_csrc[NN];        // zero-delay counts

// ---------------- fast-but-accurate math helpers ----------------
__device__ __forceinline__ float tanh_poly(float y) {
    // odd 7th-order Taylor; valid for |y| <= ~0.34 (rel err <= 4e-6, typ 1e-12)
    float y2 = y * y;
    return y * (1.0f + y2 * (-0.33333334f + y2 * (0.13333334f + y2 * (-0.05396825f))));
}

__device__ __forceinline__ float tanh_exp(float y) {
    float a = fabsf(y);
    float e = __expf(2.0f * a);
    float t = __fdividef(e - 1.0f, e + 1.0f);
    t = (a > 15.0f) ? 1.0f : t;     // also shields e == inf -> nan
    return copysignf(t, y);
}

__device__ __forceinline__ float satf(float x) {   // 1000*tanh(x/1000)
    float y = x * 0.001f;
    float r = (fabsf(y) <= 0.25f) ? tanh_poly(y) : tanh_exp(y);
    return 1000.0f * r;
}

__device__ __forceinline__ float sigf(float x) {   // 5/(1+exp(0.56*(6-x)))
    float e = __expf(0.56f * (6.0f - x));
    return __fdividef(5.0f, 1.0f + e);
}

// ---------------- precompute kernels ----------------
__global__ void k_trans(const float* __restrict__ in, const float* __restrict__ nz) {
    int idx = blockIdx.x * blockDim.x + threadIdx.x;
    if (idx >= TB*HH*NN) return;
    int n = idx % NN;
    int k = (idx / NN) % HH;
    int t = idx / (NN * HH);
    int src = (n * HH + k) * TB + t;
    g_tin[idx] = in[src];
    g_tnz[idx] = nz[src * 3];
}

__global__ void k_dt(const int* __restrict__ dist) {
    int idx = blockIdx.x * blockDim.x + threadIdx.x;
    if (idx >= NN*NN) return;
    int i = idx / NN, j = idx % NN;
    int d = (int)(((float)dist[j * NN + i]) * 0.5f);   // == trunc(dist/2.0f), exact
    g_dt[idx] = (unsigned char)d;
}

__global__ void k_wl(const float* __restrict__ wbb, const float* __restrict__ sc) {
    __shared__ double red[256];
    int tid = threadIdx.x;
    double acc = 0.0;
    for (int idx = tid; idx < NN*NN; idx += 256) {
        int i = idx / NN, j = idx % NN;
        float w1 = expf(wbb[idx])        * sc[idx];
        float w2 = expf(wbb[j*NN + i])   * sc[j*NN + i];
        float wl = log1pf(0.5f * (w1 + w2));
        g_wl[idx] = wl;
        acc += (double)wl * (double)wl;
    }
    red[tid] = acc;
    __syncthreads();
    for (int s = 128; s; s >>= 1) {
        if (tid < s) red[tid] += red[tid + s];
        __syncthreads();
    }
    if (tid == 0) g_invnorm = (float)(1.0 / sqrt(red[0]));
}

__global__ void k_wn() {
    int i = blockIdx.x * blockDim.x + threadIdx.x;
    if (i >= NN) return;
    float inv = g_invnorm;
    float rs = 0.0f;
    int c = 0;
    for (int j = 0; j < NN; ++j) {
        float wn = g_wl[i*NN + j] * inv;
        rs += wn;
        int d = g_dt[i*NN + j];
        if (d == 0) {
            if (c < MAXZ) { g_csrw[i*MAXZ + c] = wn; g_csrj[i*MAXZ + c] = j; }
            c++;
        }
        g_wl[i*NN + j] = (d == 0) ? 0.0f : wn;   // base phase excludes D==0
    }
    g_rowsum[i] = rs;
    g_csrc[i]   = (c < MAXZ) ? c : MAXZ;
}

__global__ void k_lm(const float* __restrict__ lm) {
    int tid = threadIdx.x;
    if (tid < OUTD) {
        float s = 0.0f;
        for (int j = 0; j < NN; ++j) s += fabsf(lm[tid*NN + j]);
        for (int j = 0; j < NN; ++j) g_lm1[tid*NN + j] = lm[tid*NN + j] / s;
    }
    __syncthreads();
    if (tid < NN) {
        float cs = 0.0f;
        for (int o = 0; o < OUTD; ++o) cs += g_lm1[o*NN + tid];
        cs *= (1.0f / OUTD);
        for (int o = 0; o < OUTD; ++o) g_lmt[o*NN + tid] = g_lm1[o*NN + tid] - cs;
    }
}

// ---------------- main persistent simulation kernel (1 CTA) ----------------
__global__ __launch_bounds__(NTH, 1) void k_main(
    const float* __restrict__ hx, const float* __restrict__ hE,
    float* __restrict__ out)
{
    extern __shared__ float sm[];
    float* hist    = sm;                    // [HSLOT][HP]  ring of M_final(s) at slot s&63
    float* Msh0    = hist + HSLOT*HP;       // [NN] double buffer of live M
    float* Msh1    = Msh0 + NN;
    float* base_sh = Msh1 + NN;             // [NN]
    float* emi     = base_sh + NN;          // [NN]  E-I for eeg
    float* part    = emi + NN;              // [NTH] eeg partial sums

    int tid = threadIdx.x;
    int n = tid;
    bool act = (tid < NN);

    for (int s = tid; s < HSLOT*HP; s += NTH) hist[s] = 0.0f;

    float M=0,E=0,I=0,Mv=0,Ev=0,Iv=0,rs=0;
    int zc = 0;
    if (act) {
        M  = hx[n*6+0]; E  = hx[n*6+1]; I  = hx[n*6+2];
        Mv = hx[n*6+3]; Ev = hx[n*6+4]; Iv = hx[n*6+5];
        rs = g_rowsum[n];
        zc = g_csrc[n];
    }
    __syncthreads();
    if (act) {
        Msh0[n] = hE[n*500];                              // hEb[:,0] initial
        for (int k = 1; k <= 49; ++k)                     // Mf(-k) = hE[:,k]
            hist[(HSLOT - k)*HP + n] = hE[n*500 + k];
    }
    __syncthreads();

    int p = 0;
    int w = tid >> 5, lane = tid & 31;

    for (int t = 0; t < TB; ++t) {
        // ---- base phase: base[i] = sum_{j, D>=1} w_n[i,j] * Mf(t - D[j,i]) ----
        for (int i = w; i < NN; i += (NTH/32)) {
            const float*         wr = g_wl + i*NN;
            const unsigned char* dr = g_dt + i*NN;
            float acc = 0.0f;
            for (int j = lane; j < NN; j += 32) {
                int s2 = (t - (int)dr[j]) & (HSLOT - 1);
                acc += wr[j] * hist[s2*HP + j];
            }
            #pragma unroll
            for (int o = 16; o; o >>= 1) acc += __shfl_down_sync(0xffffffffu, acc, o);
            if (lane == 0) base_sh[i] = acc;
        }
        __syncthreads();

        const float* up  = g_tin + t*HH*NN + n;
        const float* nzp = g_tnz + t*HH*NN + n;
        float u_n = 0.0f, z_n = 0.0f;
        if (act) { u_n = up[0]; z_n = nzp[0]; }

        // ---- inner loop: 20 Euler steps ----
        for (int k = 0; k < HH; ++k) {
            if (act) {
                float u = u_n, z = z_n;
                if (k + 1 < HH) { u_n = up[(k+1)*NN]; z_n = nzp[(k+1)*NN]; }

                const float* mp = p ? Msh1 : Msh0;
                float led = base_sh[n];
                for (int e = 0; e < zc; ++e)
                    led += g_csrw[n*MAXZ + e] * mp[g_csrj[n*MAXZ + e]];

                float rM = sigf(E - I);
                float rE = 250.0f*z + 1000.01f*(led - rs*E) + 108.01f*sigf(135.01f*M);
                float rI = 33.76f * sigf(33.76f*M);

                float sM = 500.0f * tanh_poly(rM * 0.002f);  // rM in (0,5)
                float sE = 500.0f * tanh_exp (rE * 0.002f);  // unbounded
                float sI = 500.0f * tanh_poly(rI * 0.002f);  // rI in (0,168.8)

                float dM  = M + 1e-4f*Mv;
                float dE  = E + 1e-4f*Ev;
                float dI  = I + 1e-4f*Iv;
                float dMv = Mv + 1e-4f*(328.25f*sM                 - 202.0f*Mv - 10201.0f*M);
                float dEv = Ev + 1e-4f*(328.25f*(5.5f*u + sE)      - 202.0f*Ev - 10201.0f*E);
                float dIv = Iv + 1e-4f*(1122.0f*sI                 - 102.0f*Iv -  2601.0f*I);

                M  = satf(dM);  E  = satf(dE);  I  = satf(dI);
                Mv = satf(dMv); Ev = satf(dEv); Iv = satf(dIv);

                float* mw = p ? Msh0 : Msh1;
                mw[n] = M;
            }
            __syncthreads();
            p ^= 1;
        }

        // ---- outer epilogue: push Mf(t), compute eeg ----
        if (act) {
            hist[(t & (HSLOT - 1))*HP + n] = M;
            emi[n] = E - I;
        }
        __syncthreads();
        {
            int o = tid >> 3, q = tid & 7;
            const float* lr = g_lmt + o*NN + q*25;
            const float* er = emi + q*25;
            float s = 0.0f;
            #pragma unroll
            for (int i2 = 0; i2 < 25; ++i2) s += lr[i2] * er[i2];
            part[tid] = s;
        }
        __syncthreads();
        if (tid < OUTD) {
            float s = 0.0f;
            #pragma unroll
            for (int q = 0; q < 8; ++q) s += part[tid*8 + q];
            out[tid*TB + t] = 5.0f * s - 2.0f;
        }
        // no barrier needed: next base phase touches only hist/base_sh,
        // both already synchronized above; part/emi rewritten after 20+ barriers
    }

    if (act) {
        float* st = out + OUTD*TB + n*6;
        st[0] = M;  st[1] = E;  st[2] = I;
        st[3] = Mv; st[4] = Ev; st[5] = Iv;
    }
}

// ---------------- harness entry ----------------
extern "C" void kernel_launch(void* const* d_in, const int* in_sizes, int n_in,
                              void* d_out, int out_size) {
    const float* input    = (const float*)d_in[0];
    const float* noise_in = (const float*)d_in[1];
    // d_in[2] = noise_out (unused by reference)
    const float* hx       = (const float*)d_in[3];
    const float* hE       = (const float*)d_in[4];
    const float* wbb      = (const float*)d_in[5];
    const float* lm       = (const float*)d_in[6];
    const float* sc       = (const float*)d_in[7];
    const int*   dist     = (const int*)d_in[8];
    float*       out      = (float*)d_out;

    cudaFuncSetAttribute(k_main, cudaFuncAttributeMaxDynamicSharedMemorySize, SMEM_BYTES);

    k_trans<<<(TB*HH*NN + 255)/256, 256>>>(input, noise_in);
    k_dt  <<<(NN*NN + 255)/256, 256>>>(dist);
    k_wl  <<<1, 256>>>(wbb, sc);
    k_wn  <<<1, 256>>>();
    k_lm  <<<1, 256>>>(lm);
    k_main<<<1, NTH, SMEM_BYTES>>>(hx, hE, out);
}

// round 2
// speedup vs baseline: 1.4977x; 1.4977x over previous
#include <cuda_runtime.h>
#include <stdint.h>

#define NN    200
#define HH    20
#define TB    400
#define OUTD  64
#define HP    201
#define NTH   512
#define NCONS 224       // consumer threads: warps 0-6
#define K0    16        // unrolled zero-delay CSR slots (mean count ~4)
#define X0    32        // zero-delay spill capacity
#define K1    48        // delay==1 capacity (mean ~4)
#define P2CAP 200       // delay>=2 capacity (max possible)

// shared: hist 64*201 + MA 208 + MB 208 + b2 2*208 + emi 2*208 + ush 20*200 + zsh 20*200
#define SMEM_FLOATS (64*HP + 208 + 208 + 2*208 + 2*208 + HH*NN + HH*NN)
#define SMEM_BYTES  (SMEM_FLOATS * 4)

// ---------------- device scratch ----------------
__device__ float g_wl [NN*NN];
__device__ float g_w0 [NN*K0];
__device__ int   g_o0 [NN*K0];
__device__ uint2 g_x0 [NN*X0];  __device__ int g_x0c[NN];
__device__ uint2 g_e1 [NN*K1];  __device__ int g_e1c[NN];
__device__ uint2 g_p2 [NN*P2CAP]; __device__ int g_p2c[NN];
__device__ float g_rowsum[NN];
__device__ float g_lm1[OUTD*NN];
__device__ float g_lmt[OUTD*NN];

// ---------------- math helpers ----------------
// Pade(5,6) for tanh, |y| <= 3: rel err ~3e-7 @2.0, ~2.4e-6 @2.5
__device__ __forceinline__ float padeth(float y) {
    float z = y * y;
    float num = y * fmaf(z, fmaf(z, 21.0f, 1260.0f), 10395.0f);
    float den = fmaf(z, fmaf(z, fmaf(z, 1.0f, 210.0f), 4725.0f), 10395.0f);
    return __fdividef(num, den);
}
__device__ __forceinline__ float satp(float x) {   // 1000*tanh(x/1000); |x/1000| <= ~2.1 by algebra
    float y = x * 0.001f;
    y = fminf(fmaxf(y, -3.0f), 3.0f);
    return 1000.0f * padeth(y);
}
__device__ __forceinline__ float tanh_tiny(float y) {   // |y| <= 0.01
    return y * fmaf(-0.33333334f, y * y, 1.0f);
}
__device__ __forceinline__ float tanh_big(float y) {    // unbounded arg
    float a = fabsf(y);
    float e = __expf(2.0f * a);
    float t = __fdividef(e - 1.0f, e + 1.0f);
    t = (a > 15.0f) ? 1.0f : t;
    return copysignf(t, y);
}
__device__ __forceinline__ float sigf(float x) {        // 5/(1+exp(0.56*(6-x)))
    float e = __expf(0.56f * (6.0f - x));
    return __fdividef(5.0f, 1.0f + e);
}

// ---------------- precompute: one block, 256 threads ----------------
__global__ void k_pre(const float* __restrict__ wbb, const float* __restrict__ sc,
                      const int* __restrict__ dist, const float* __restrict__ lm) {
    __shared__ double red[256];
    int tid = threadIdx.x;
    double acc = 0.0;
    for (int idx = tid; idx < NN*NN; idx += 256) {
        int i = idx / NN, j = idx % NN;
        float w1 = expf(wbb[idx])      * sc[idx];
        float w2 = expf(wbb[j*NN + i]) * sc[j*NN + i];
        float wl = log1pf(0.5f * (w1 + w2));
        g_wl[idx] = wl;
        acc += (double)wl * (double)wl;
    }
    red[tid] = acc; __syncthreads();
    for (int s = 128; s; s >>= 1) { if (tid < s) red[tid] += red[tid + s]; __syncthreads(); }
    float inv = (float)(1.0 / sqrt(red[0]));

    if (tid < NN) {
        int i = tid;
        float rs = 0.0f;
        int c0 = 0, cx = 0, c1 = 0, c2 = 0;
        for (int j = 0; j < NN; ++j) {
            float wn = g_wl[i*NN + j] * inv;
            rs += wn;
            int d = dist[j*NN + i] >> 1;    // delays = trunc(dist/2), dist in [0,100)
            if (d == 0) {
                if (c0 < K0) { g_w0[i*K0 + c0] = wn; g_o0[i*K0 + c0] = j; c0++; }
                else if (cx < X0) { g_x0[i*X0 + cx] = make_uint2(__float_as_uint(wn), (unsigned)j); cx++; }
            } else if (d == 1) {
                if (c1 < K1) { g_e1[i*K1 + c1] = make_uint2(__float_as_uint(wn), (unsigned)j); c1++; }
            } else {
                g_p2[i*P2CAP + c2] = make_uint2(__float_as_uint(wn), ((unsigned)d << 16) | (unsigned)j); c2++;
            }
        }
        for (; c0 < K0; ++c0) { g_w0[i*K0 + c0] = 0.0f; g_o0[i*K0 + c0] = 0; }
        g_x0c[i] = cx; g_e1c[i] = c1; g_p2c[i] = c2; g_rowsum[i] = rs;
    }
    __syncthreads();
    if (tid < OUTD) {
        float s = 0.0f;
        for (int j = 0; j < NN; ++j) s += fabsf(lm[tid*NN + j]);
        float invs = 1.0f / s;
        for (int j = 0; j < NN; ++j) g_lm1[tid*NN + j] = lm[tid*NN + j] * invs;
    }
    __syncthreads();
    if (tid < NN) {
        float cs = 0.0f;
        for (int o = 0; o < OUTD; ++o) cs += g_lm1[o*NN + tid];
        cs *= (1.0f / OUTD);
        for (int o = 0; o < OUTD; ++o) g_lmt[o*NN + tid] = g_lm1[o*NN + tid] - cs;
    }
}

// ---------------- main persistent kernel: 1 CTA, warp-specialized ----------------
__global__ __launch_bounds__(NTH, 1) void k_main(
    const float* __restrict__ input, const float* __restrict__ noise,
    const float* __restrict__ hx, const float* __restrict__ hE,
    float* __restrict__ out)
{
    extern __shared__ float sm[];
    float* hist = sm;                 // [64][HP]   Mf history ring (+ hE prehistory)
    float* MA   = hist + 64*HP;       // [208] live-M ping
    float* MB   = MA + 208;           // [208] live-M pong
    float* b2   = MB + 208;           // [2][208] D>=2 coupling, double-buffered by t parity
    float* emi  = b2 + 2*208;         // [2][208] E-I, double-buffered
    float* ush  = emi + 2*208;        // [HH][NN] staged input
    float* zsh  = ush + HH*NN;        // [HH][NN] staged noise

    int tid = threadIdx.x;

    // ---- init: zero hist, load prehistory + live M ----
    for (int s = tid; s < 64*HP; s += NTH) hist[s] = 0.0f;
    __syncthreads();
    if (tid < NN) {
        MA[tid] = hE[tid*500];                              // hEb[:,0] initial
        for (int k = 1; k <= 49; ++k)
            hist[((0 - k) & 63)*HP + tid] = hE[tid*500 + k]; // Mf(-k) = hE[:,k]
    }
    __syncthreads();

    // ---- base2 for t=0 (all 16 warps) ----
    {
        int w = tid >> 5, l = tid & 31;
        for (int row = w; row < NN; row += 16) {
            const uint2* pp = g_p2 + row*P2CAP;
            int cnt = g_p2c[row];
            float a = 0.0f;
            for (int m = l; m < cnt; m += 32) {
                uint2 v = pp[m];
                int j = v.y & 0xffff, D = v.y >> 16;
                a = fmaf(__uint_as_float(v.x), hist[((0 - D) & 63)*HP + j], a);
            }
            #pragma unroll
            for (int o = 16; o; o >>= 1) a += __shfl_down_sync(0xffffffffu, a, o);
            if (!l) b2[0*208 + row] = a;
        }
    }
    __syncthreads();

    if (tid < NCONS) {
        // ================= CONSUMER: warps 0-6 =================
        int n = tid;
        bool act = (n < NN);
        float M=0,E=0,I=0,Mv=0,Ev=0,Iv=0,rs=0;
        float w0[K0]; int o0[K0];
        int xc = 0, e1c = 0;
        if (act) {
            M  = hx[n*6+0]; E  = hx[n*6+1]; I  = hx[n*6+2];
            Mv = hx[n*6+3]; Ev = hx[n*6+4]; Iv = hx[n*6+5];
            rs = g_rowsum[n]; xc = g_x0c[n]; e1c = g_e1c[n];
            #pragma unroll
            for (int e = 0; e < K0; ++e) { w0[e] = g_w0[n*K0 + e]; o0[e] = g_o0[n*K0 + e]; }
        }

        for (int t = 0; t < TB; ++t) {
            // stage u/z for all 20 inner steps (high MLP)
            for (int idx = tid; idx < HH*NN; idx += NCONS) {
                int kk = idx / NN, n2 = idx - kk*NN;
                int src = (n2*HH + kk)*TB + t;
                ush[idx] = input[src];
                zsh[idx] = noise[src*3];
            }
            // D>=2 base (produced last phase) + D==1 contribution (once per outer step)
            float base = 0.0f;
            if (act) {
                base = b2[(t & 1)*208 + n];
                int sl = ((t - 1) & 63)*HP;
                const uint2* e1 = g_e1 + n*K1;
                for (int e = 0; e < e1c; ++e) {
                    uint2 v = e1[e];
                    base = fmaf(__uint_as_float(v.x), hist[sl + (int)v.y], base);
                }
            }
            asm volatile("bar.sync 1, 224;" ::: "memory");

            #pragma unroll 2
            for (int k = 0; k < HH; ++k) {
                const float* rd = (k & 1) ? MB : MA;
                float*       wr = (k & 1) ? MA : MB;
                if (act) {
                    // M update first: it's the only cross-thread dependency
                    float mnew = satp(fmaf(1e-4f, Mv, M));
                    wr[n] = mnew;
                    // zero-delay gather from register CSR
                    float led = base;
                    #pragma unroll
                    for (int e = 0; e < K0; ++e) led = fmaf(w0[e], rd[o0[e]], led);
                    if (xc) {
                        const uint2* xp = g_x0 + n*X0;
                        for (int e = 0; e < xc; ++e) {
                            uint2 v = xp[e];
                            led = fmaf(__uint_as_float(v.x), rd[(int)v.y], led);
                        }
                    }
                    float u = ush[k*NN + n], z = zsh[k*NN + n];
                    float rM  = sigf(E - I);
                    float sgM = sigf(135.01f * M);
                    float rI  = 33.76f * sigf(33.76f * M);
                    float rE  = fmaf(250.0f, z, fmaf(1000.01f, led - rs*E, 108.01f * sgM));
                    float sM  = 500.0f * tanh_tiny(rM * 0.002f);   // rM in (0,5)
                    float sI  = 500.0f * padeth(rI * 0.002f);      // rI in (0,169)
                    float sE  = 500.0f * tanh_big(rE * 0.002f);    // unbounded
                    float En  = satp(fmaf(1e-4f, Ev, E));
                    float In  = satp(fmaf(1e-4f, Iv, I));
                    float Mvn = satp(fmaf(1e-4f, fmaf(328.25f, sM,                  fmaf(-202.0f, Mv, -10201.0f*M)), Mv));
                    float Evn = satp(fmaf(1e-4f, fmaf(328.25f, fmaf(5.5f, u, sE),   fmaf(-202.0f, Ev, -10201.0f*E)), Ev));
                    float Ivn = satp(fmaf(1e-4f, fmaf(1122.0f, sI,                  fmaf(-102.0f, Iv,  -2601.0f*I)), Iv));
                    M = mnew; E = En; I = In; Mv = Mvn; Ev = Evn; Iv = Ivn;
                }
                asm volatile("bar.sync 1, 224;" ::: "memory");
            }
            if (act) {
                hist[(t & 63)*HP + n] = M;
                emi[(t & 1)*208 + n]  = E - I;
            }
            __syncthreads();
        }
        if (act) {
            float* st = out + OUTD*TB + n*6;
            st[0] = M;  st[1] = E;  st[2] = I;
            st[3] = Mv; st[4] = Ev; st[5] = Iv;
        }
    } else {
        // ================= PRODUCER: warps 7-15 (288 threads) =================
        int ptid = tid - NCONS;
        int pw = ptid >> 5, pl = ptid & 31;
        for (int t = 0; t < TB; ++t) {
            // eeg for step t-1 (warps 7-8)
            if (t && ptid < OUTD) {
                const float* lr = g_lmt + ptid*NN;
                const float* er = emi + ((t - 1) & 1)*208;
                float s = 0.0f;
                #pragma unroll 8
                for (int i = 0; i < NN; ++i) s = fmaf(lr[i], er[i], s);
                out[ptid*TB + (t - 1)] = fmaf(5.0f, s, -2.0f);
            }
            // D>=2 base for step t+1 (all 9 warps, warp-per-row)
            int tn = t + 1;
            for (int row = pw; row < NN; row += 9) {
                const uint2* pp = g_p2 + row*P2CAP;
                int cnt = g_p2c[row];
                float a = 0.0f;
                for (int m = pl; m < cnt; m += 32) {
                    uint2 v = pp[m];
                    int j = v.y & 0xffff, D = v.y >> 16;
                    a = fmaf(__uint_as_float(v.x), hist[((tn - D) & 63)*HP + j], a);
                }
                #pragma unroll
                for (int o = 16; o; o >>= 1) a += __shfl_down_sync(0xffffffffu, a, o);
                if (!pl) b2[(tn & 1)*208 + row] = a;
            }
            __syncthreads();
        }
        // final eeg (t = TB-1): emi visible after the last full barrier above
        if (ptid < OUTD) {
            const float* lr = g_lmt + ptid*NN;
            const float* er = emi + ((TB - 1) & 1)*208;
            float s = 0.0f;
            #pragma unroll 8
            for (int i = 0; i < NN; ++i) s = fmaf(lr[i], er[i], s);
            out[ptid*TB + (TB - 1)] = fmaf(5.0f, s, -2.0f);
        }
    }
}

// ---------------- harness entry ----------------
extern "C" void kernel_launch(void* const* d_in, const int* in_sizes, int n_in,
                              void* d_out, int out_size) {
    const float* input    = (const float*)d_in[0];
    const float* noise_in = (const float*)d_in[1];
    // d_in[2] = noise_out (unused by reference)
    const float* hx       = (const float*)d_in[3];
    const float* hE       = (const float*)d_in[4];
    const float* wbb      = (const float*)d_in[5];
    const float* lm       = (const float*)d_in[6];
    const float* sc       = (const float*)d_in[7];
    const int*   dist     = (const int*)d_in[8];
    float*       out      = (float*)d_out;

    cudaFuncSetAttribute(k_main, cudaFuncAttributeMaxDynamicSharedMemorySize, SMEM_BYTES);

    k_pre <<<1, 256>>>(wbb, sc, dist, lm);
    k_main<<<1, NTH, SMEM_BYTES>>>(input, noise_in, hx, hE, out);
}

// round 3
// speedup vs baseline: 3.5413x; 2.3645x over previous
#include <cuda_runtime.h>
#include <stdint.h>

#define NN    200
#define HH    20
#define TB    400
#define OUTD  64
#define HP    201
#define NTH   512
#define NCONS 224        // consumer threads: warps 0-6
#define NPROD (NTH-NCONS)// producer threads: warps 7-15 (288)
#define K0    16         // unrolled zero-delay CSR slots
#define X0    32         // zero-delay spill capacity
#define K1    48         // delay==1 capacity
#define P2SLOT 224       // padded D>=2 entries per row (7 per lane)
#define P2PER  7

// smem: hist 64*201 + MA/MB 2*208 + b2 2*208 + emi 2*208 + ush 2*20*200 + zsh 2*20*200
#define SMEM_FLOATS (64*HP + 2*208 + 2*208 + 2*208 + 2*HH*NN + 2*HH*NN)
#define SMEM_BYTES  (SMEM_FLOATS * 4)

// ---------------- device scratch ----------------
__device__ __align__(16) float g_tin[TB*HH*NN];   // (t,k,n)
__device__ __align__(16) float g_tnz[TB*HH*NN];   // (t,k,n)
__device__ float g_wl [NN*NN];
__device__ float g_w0 [NN*K0];
__device__ int   g_o0 [NN*K0];
__device__ uint2 g_x0 [NN*X0];    __device__ int g_x0c[NN];
__device__ uint2 g_e1 [NN*K1];    __device__ int g_e1c[NN];
__device__ uint2 g_p2 [NN*P2SLOT];                 // padded to fixed 224/row
__device__ float g_rowsum[NN];
__device__ float g_lm1[OUTD*NN];
__device__ float g_lmt[OUTD*NN];

// ---------------- math helpers ----------------
__device__ __forceinline__ float padeth(float y) {     // tanh, |y|<=3, rel err <=2.4e-6
    float z = y * y;
    float num = y * fmaf(z, fmaf(z, 21.0f, 1260.0f), 10395.0f);
    float den = fmaf(z, fmaf(z, fmaf(z, 1.0f, 210.0f), 4725.0f), 10395.0f);
    return __fdividef(num, den);
}
__device__ __forceinline__ float satp(float x) {        // 1000*tanh(x/1000)
    float y = x * 0.001f;
    y = fminf(fmaxf(y, -3.0f), 3.0f);
    return 1000.0f * padeth(y);
}
__device__ __forceinline__ float tanh_tiny(float y) {   // |y| <= 0.01
    return y * fmaf(-0.33333334f, y * y, 1.0f);
}
__device__ __forceinline__ float tanh_big(float y) {    // unbounded
    float a = fabsf(y);
    float e = __expf(2.0f * a);
    float t = __fdividef(e - 1.0f, e + 1.0f);
    t = (a > 15.0f) ? 1.0f : t;
    return copysignf(t, y);
}
__device__ __forceinline__ float sigf(float x) {        // 5/(1+exp(0.56*(6-x)))
    float e = __expf(0.56f * (6.0f - x));
    return __fdividef(5.0f, 1.0f + e);
}

// ---------------- transpose: coalesced read, scattered write ----------------
__global__ void k_trans(const float* __restrict__ in, const float* __restrict__ nz) {
    int idx = blockIdx.x * blockDim.x + threadIdx.x;   // == src index
    if (idx >= TB*HH*NN) return;
    int t = idx % TB;
    int k = (idx / TB) % HH;
    int n = idx / (TB * HH);
    int dst = (t*HH + k)*NN + n;
    g_tin[dst] = in[idx];
    g_tnz[dst] = nz[idx * 3];
}

// ---------------- precompute: one block, 256 threads ----------------
__global__ void k_pre(const float* __restrict__ wbb, const float* __restrict__ sc,
                      const int* __restrict__ dist, const float* __restrict__ lm) {
    __shared__ double red[256];
    int tid = threadIdx.x;
    double acc = 0.0;
    for (int idx = tid; idx < NN*NN; idx += 256) {
        int i = idx / NN, j = idx % NN;
        float w1 = expf(wbb[idx])      * sc[idx];
        float w2 = expf(wbb[j*NN + i]) * sc[j*NN + i];
        float wl = log1pf(0.5f * (w1 + w2));
        g_wl[idx] = wl;
        acc += (double)wl * (double)wl;
    }
    red[tid] = acc; __syncthreads();
    for (int s = 128; s; s >>= 1) { if (tid < s) red[tid] += red[tid + s]; __syncthreads(); }
    float inv = (float)(1.0 / sqrt(red[0]));

    if (tid < NN) {
        int i = tid;
        float rs = 0.0f;
        int c0 = 0, cx = 0, c1 = 0, c2 = 0;
        for (int j = 0; j < NN; ++j) {
            float wn = g_wl[i*NN + j] * inv;
            rs += wn;
            int d = dist[j*NN + i] >> 1;    // trunc(dist/2.0)
            if (d == 0) {
                if (c0 < K0) { g_w0[i*K0 + c0] = wn; g_o0[i*K0 + c0] = j; c0++; }
                else if (cx < X0) { g_x0[i*X0 + cx] = make_uint2(__float_as_uint(wn), (unsigned)j); cx++; }
            } else if (d == 1) {
                if (c1 < K1) { g_e1[i*K1 + c1] = make_uint2(__float_as_uint(wn), (unsigned)j); c1++; }
            } else {
                g_p2[i*P2SLOT + c2] = make_uint2(__float_as_uint(wn), ((unsigned)d << 16) | (unsigned)j); c2++;
            }
        }
        for (; c0 < K0; ++c0) { g_w0[i*K0 + c0] = 0.0f; g_o0[i*K0 + c0] = 0; }
        for (; c2 < P2SLOT; ++c2) g_p2[i*P2SLOT + c2] = make_uint2(0u, (2u << 16));  // w=0 pad
        g_x0c[i] = cx; g_e1c[i] = c1; g_rowsum[i] = rs;
    }
    __syncthreads();
    if (tid < OUTD) {
        float s = 0.0f;
        for (int j = 0; j < NN; ++j) s += fabsf(lm[tid*NN + j]);
        float invs = 1.0f / s;
        for (int j = 0; j < NN; ++j) g_lm1[tid*NN + j] = lm[tid*NN + j] * invs;
    }
    __syncthreads();
    if (tid < NN) {
        float cs = 0.0f;
        for (int o = 0; o < OUTD; ++o) cs += g_lm1[o*NN + tid];
        cs *= (1.0f / OUTD);
        for (int o = 0; o < OUTD; ++o) g_lmt[o*NN + tid] = g_lm1[o*NN + tid] - cs;
    }
}

// ---------------- main persistent kernel: 1 CTA, warp-specialized ----------------
__global__ __launch_bounds__(NTH, 1) void k_main(
    const float* __restrict__ hx, const float* __restrict__ hE,
    float* __restrict__ out)
{
    extern __shared__ float sm[];
    float* hist = sm;                  // [64][HP]  Mf history ring (+ hE prehistory)
    float* MA   = hist + 64*HP;        // [208]
    float* MB   = MA + 208;            // [208]
    float* b2   = MB + 208;            // [2][208]  D>=2 coupling, parity by t
    float* emi  = b2 + 2*208;          // [2][208]  E-I, parity by t
    float* ush  = emi + 2*208;         // [2][HH*NN] staged input, parity by t
    float* zsh  = ush + 2*HH*NN;       // [2][HH*NN] staged noise, parity by t

    int tid = threadIdx.x;

    // ---- init ----
    for (int s = tid; s < 64*HP; s += NTH) hist[s] = 0.0f;
    __syncthreads();
    if (tid < NN) {
        MA[tid] = hE[tid*500];
        for (int k = 1; k <= 49; ++k)
            hist[((0 - k) & 63)*HP + tid] = hE[tid*500 + k];
    }
    // stage t=0 (parity 0), all threads, vectorized
    {
        const float4* s1 = (const float4*)g_tin;
        const float4* s2 = (const float4*)g_tnz;
        float4* d1 = (float4*)ush;
        float4* d2 = (float4*)zsh;
        for (int i = tid; i < HH*NN/4; i += NTH) { d1[i] = s1[i]; d2[i] = s2[i]; }
    }
    __syncthreads();
    // b2 for t=0 (parity 0), all 16 warps
    {
        int w = tid >> 5, l = tid & 31;
        for (int row = w; row < NN; row += 16) {
            const uint2* pp = g_p2 + row*P2SLOT;
            float a = 0.0f;
            #pragma unroll
            for (int e = 0; e < P2PER; ++e) {
                uint2 v = pp[e*32 + l];
                int j = v.y & 0xffff, D = v.y >> 16;
                a = fmaf(__uint_as_float(v.x), hist[((0 - D) & 63)*HP + j], a);
            }
            #pragma unroll
            for (int o = 16; o; o >>= 1) a += __shfl_down_sync(0xffffffffu, a, o);
            if (!l) b2[row] = a;
        }
    }
    __syncthreads();

    if (tid < NCONS) {
        // ================= CONSUMERS: warps 0-6 =================
        int n = tid;
        bool act = (n < NN);
        float M=0,E=0,I=0,Mv=0,Ev=0,Iv=0,rs=0;
        float w0[K0]; int o0[K0];
        int xc = 0, e1c = 0;
        if (act) {
            M  = hx[n*6+0]; E  = hx[n*6+1]; I  = hx[n*6+2];
            Mv = hx[n*6+3]; Ev = hx[n*6+4]; Iv = hx[n*6+5];
            rs = g_rowsum[n]; xc = g_x0c[n]; e1c = g_e1c[n];
            #pragma unroll
            for (int e = 0; e < K0; ++e) { w0[e] = g_w0[n*K0 + e]; o0[e] = g_o0[n*K0 + e]; }
        }

        for (int t = 0; t < TB; ++t) {
            int par = t & 1;
            const float* uk = ush + par*HH*NN + n;
            const float* zk = zsh + par*HH*NN + n;
            float base = 0.0f;
            if (act) {
                base = b2[par*208 + n];
                int sl = ((t - 1) & 63)*HP;
                const uint2* e1 = g_e1 + n*K1;
                for (int e = 0; e < e1c; ++e) {
                    uint2 v = e1[e];
                    base = fmaf(__uint_as_float(v.x), hist[sl + (int)v.y], base);
                }
            }
            asm volatile("bar.sync 1, 224;" ::: "memory");

            #pragma unroll 2
            for (int k = 0; k < HH; ++k) {
                const float* rd = (k & 1) ? MB : MA;
                float*       wr = (k & 1) ? MA : MB;
                if (act) {
                    float mnew = satp(fmaf(1e-4f, Mv, M));
                    wr[n] = mnew;
                    float l0 = base, l1 = 0.0f, l2 = 0.0f, l3 = 0.0f;
                    #pragma unroll
                    for (int e = 0; e < K0; e += 4) {
                        l0 = fmaf(w0[e+0], rd[o0[e+0]], l0);
                        l1 = fmaf(w0[e+1], rd[o0[e+1]], l1);
                        l2 = fmaf(w0[e+2], rd[o0[e+2]], l2);
                        l3 = fmaf(w0[e+3], rd[o0[e+3]], l3);
                    }
                    float led = (l0 + l1) + (l2 + l3);
                    if (xc) {
                        const uint2* xp = g_x0 + n*X0;
                        for (int e = 0; e < xc; ++e) {
                            uint2 v = xp[e];
                            led = fmaf(__uint_as_float(v.x), rd[(int)v.y], led);
                        }
                    }
                    float u = uk[k*NN], z = zk[k*NN];
                    float rM  = sigf(E - I);
                    float sgM = sigf(135.01f * M);
                    float rI  = 33.76f * sigf(33.76f * M);
                    float rE  = fmaf(250.0f, z, fmaf(1000.01f, led - rs*E, 108.01f * sgM));
                    float sM  = 500.0f * tanh_tiny(rM * 0.002f);
                    float sI  = 500.0f * padeth(rI * 0.002f);
                    float sE  = 500.0f * tanh_big(rE * 0.002f);
                    float En  = satp(fmaf(1e-4f, Ev, E));
                    float In  = satp(fmaf(1e-4f, Iv, I));
                    float Mvn = satp(fmaf(1e-4f, fmaf(328.25f, sM,                fmaf(-202.0f, Mv, -10201.0f*M)), Mv));
                    float Evn = satp(fmaf(1e-4f, fmaf(328.25f, fmaf(5.5f, u, sE), fmaf(-202.0f, Ev, -10201.0f*E)), Ev));
                    float Ivn = satp(fmaf(1e-4f, fmaf(1122.0f, sI,                fmaf(-102.0f, Iv,  -2601.0f*I)), Iv));
                    M = mnew; E = En; I = In; Mv = Mvn; Ev = Evn; Iv = Ivn;
                }
                asm volatile("bar.sync 1, 224;" ::: "memory");
            }
            if (act) {
                hist[(t & 63)*HP + n] = M;
                emi[par*208 + n]      = E - I;
            }
            __syncthreads();
        }
        if (act) {
            float* st = out + OUTD*TB + n*6;
            st[0] = M;  st[1] = E;  st[2] = I;
            st[3] = Mv; st[4] = Ev; st[5] = Iv;
        }
    } else {
        // ================= PRODUCERS: warps 7-15 (288 threads) =================
        int ptid = tid - NCONS;
        int pw = ptid >> 5, pl = ptid & 31;
        for (int t = 0; t < TB; ++t) {
            bool more = (t + 1 < TB);
            // stage u/z for t+1 (coalesced float4)
            if (more) {
                int np = (t + 1) & 1;
                const float4* s1 = (const float4*)(g_tin + (t+1)*HH*NN);
                const float4* s2 = (const float4*)(g_tnz + (t+1)*HH*NN);
                float4* d1 = (float4*)(ush + np*HH*NN);
                float4* d2 = (float4*)(zsh + np*HH*NN);
                for (int i = ptid; i < HH*NN/4; i += NPROD) { d1[i] = s1[i]; d2[i] = s2[i]; }
            }
            // eeg for t-1 : 4 lanes per output
            if (t > 0 && ptid < 4*OUTD) {
                int o = ptid >> 2, q = ptid & 3;
                const float* lr = g_lmt + o*NN + q*50;
                const float* er = emi + ((t - 1) & 1)*208 + q*50;
                float s0 = 0.0f, s1 = 0.0f;
                #pragma unroll 5
                for (int i = 0; i < 50; i += 2) {
                    s0 = fmaf(lr[i],   er[i],   s0);
                    s1 = fmaf(lr[i+1], er[i+1], s1);
                }
                float s = s0 + s1;
                s += __shfl_down_sync(0xffffffffu, s, 2, 4);
                s += __shfl_down_sync(0xffffffffu, s, 1, 4);
                if (!q) out[o*TB + (t - 1)] = fmaf(5.0f, s, -2.0f);
            }
            // b2 for t+1 : 2 rows per iteration for ILP, fixed-trip unrolled loads
            if (more) {
                int tn = t + 1;
                float* b2d = b2 + (tn & 1)*208;
                for (int row = pw; row < NN; row += 18) {
                    int rowB = row + 9;
                    bool hasB = rowB < NN;
                    const uint2* pA = g_p2 + row*P2SLOT;
                    const uint2* pB = g_p2 + (hasB ? rowB : row)*P2SLOT;
                    float a = 0.0f, b = 0.0f;
                    #pragma unroll
                    for (int e = 0; e < P2PER; ++e) {
                        uint2 vA = pA[e*32 + pl];
                        uint2 vB = pB[e*32 + pl];
                        int jA = vA.y & 0xffff, DA = vA.y >> 16;
                        int jB = vB.y & 0xffff, DB = vB.y >> 16;
                        a = fmaf(__uint_as_float(vA.x), hist[((tn - DA) & 63)*HP + jA], a);
                        b = fmaf(__uint_as_float(vB.x), hist[((tn - DB) & 63)*HP + jB], b);
                    }
                    #pragma unroll
                    for (int o = 16; o; o >>= 1) {
                        a += __shfl_down_sync(0xffffffffu, a, o);
                        b += __shfl_down_sync(0xffffffffu, b, o);
                    }
                    if (!pl) { b2d[row] = a; if (hasB) b2d[rowB] = b; }
                }
            }
            __syncthreads();
        }
        // final eeg (t = TB-1)
        if (ptid < 4*OUTD) {
            int o = ptid >> 2, q = ptid & 3;
            const float* lr = g_lmt + o*NN + q*50;
            const float* er = emi + ((TB - 1) & 1)*208 + q*50;
            float s0 = 0.0f, s1 = 0.0f;
            #pragma unroll 5
            for (int i = 0; i < 50; i += 2) {
                s0 = fmaf(lr[i],   er[i],   s0);
                s1 = fmaf(lr[i+1], er[i+1], s1);
            }
            float s = s0 + s1;
            s += __shfl_down_sync(0xffffffffu, s, 2, 4);
            s += __shfl_down_sync(0xffffffffu, s, 1, 4);
            if (!q) out[o*TB + (TB - 1)] = fmaf(5.0f, s, -2.0f);
        }
    }
}

// ---------------- harness entry ----------------
extern "C" void kernel_launch(void* const* d_in, const int* in_sizes, int n_in,
                              void* d_out, int out_size) {
    const float* input    = (const float*)d_in[0];
    const float* noise_in = (const float*)d_in[1];
    const float* hx       = (const float*)d_in[3];
    const float* hE       = (const float*)d_in[4];
    const float* wbb      = (const float*)d_in[5];
    const float* lm       = (const float*)d_in[6];
    const float* sc       = (const float*)d_in[7];
    const int*   dist     = (const int*)d_in[8];
    float*       out      = (float*)d_out;

    cudaFuncSetAttribute(k_main, cudaFuncAttributeMaxDynamicSharedMemorySize, SMEM_BYTES);

    k_trans<<<(TB*HH*NN + 255)/256, 256>>>(input, noise_in);
    k_pre  <<<1, 256>>>(wbb, sc, dist, lm);
    k_main <<<1, NTH, SMEM_BYTES>>>(hx, hE, out);
}

// round 4
// speedup vs baseline: 3.8284x; 1.0811x over previous
#include <cuda_runtime.h>
#include <stdint.h>

#define NN    200
#define HH    20
#define TB    400
#define OUTD  64
#define HP    201
#define NTH   224
#define K0    12         // unrolled zero-delay CSR slots
#define X0    32         // zero-delay spill capacity (global, rare)
#define K1    48         // delay==1 capacity
#define P2SLOT 224       // padded D>=2 entries per row (7 per lane)
#define CLU   8

// smem: hist 64*201 + MA 208 + MB 208 + b2 2*208 + emi 2*208
#define SMEM_FLOATS (64*HP + 208 + 208 + 2*208 + 2*208)
#define SMEM_BYTES  (SMEM_FLOATS * 4)

// ---------------- device scratch ----------------
__device__ __align__(16) float g_tin[TB*HH*NN];   // (t,k,n)
__device__ __align__(16) float g_tnz[TB*HH*NN];   // (t,k,n)
__device__ float g_wl [NN*NN];
__device__ float g_w0 [NN*K0];
__device__ int   g_o0 [NN*K0];
__device__ uint2 g_x0 [NN*X0];    __device__ int g_x0c[NN];
__device__ uint2 g_e1 [NN*K1];    __device__ int g_e1c[NN];
__device__ uint2 g_p2 [NN*P2SLOT];
__device__ float g_rowsum[NN];
__device__ float g_lm1[OUTD*NN];
__device__ float g_lmt[OUTD*NN];

// ---------------- cluster / mbarrier helpers ----------------
__device__ __forceinline__ uint32_t smem_u32(const void* p) {
    uint32_t a;
    asm("{ .reg .u64 t; cvta.to.shared.u64 t, %1; cvt.u32.u64 %0, t; }" : "=r"(a) : "l"(p));
    return a;
}
__device__ __forceinline__ uint32_t ctarank() {
    uint32_t r; asm("mov.u32 %0, %%cluster_ctarank;" : "=r"(r)); return r;
}
__device__ __forceinline__ void mbar_init(uint32_t a, uint32_t cnt) {
    asm volatile("mbarrier.init.shared.b64 [%0], %1;" :: "r"(a), "r"(cnt) : "memory");
}
__device__ __forceinline__ void fence_cluster() {
    asm volatile("fence.acq_rel.cluster;" ::: "memory");
}
__device__ __forceinline__ void mbar_wait_cl(uint32_t mbar, uint32_t parity) {
    asm volatile(
        "{\n\t.reg .pred P;\n"
        "W%=:\n\t"
        "mbarrier.try_wait.parity.acquire.cluster.shared::cta.b64 P, [%0], %1, 0x989680;\n\t"
        "@P bra.uni D%=;\n\t"
        "bra.uni W%=;\n"
        "D%=:\n\t}"
        :: "r"(mbar), "r"(parity) : "memory");
}
__device__ __forceinline__ void mbar_arrive_rk(uint32_t mbar_local, uint32_t rk) {
    uint32_t rem;
    asm volatile("mapa.shared::cluster.u32 %0, %1, %2;" : "=r"(rem) : "r"(mbar_local), "r"(rk));
    asm volatile("mbarrier.arrive.release.cluster.shared::cluster.b64 _, [%0];" :: "r"(rem) : "memory");
}
__device__ __forceinline__ void st_rk_f32(uint32_t local, uint32_t rk, float v) {
    uint32_t rem;
    asm volatile("mapa.shared::cluster.u32 %0, %1, %2;" : "=r"(rem) : "r"(local), "r"(rk));
    asm volatile("st.shared::cluster.f32 [%0], %1;" :: "r"(rem), "f"(v) : "memory");
}
#define CLUSTER_SYNC() do { \
    asm volatile("barrier.cluster.arrive.aligned;" ::: "memory"); \
    asm volatile("barrier.cluster.wait.aligned;"  ::: "memory"); \
} while (0)

// ---------------- math helpers (identical to validated R3) ----------------
__device__ __forceinline__ float padeth(float y) {     // tanh, |y|<=3
    float z = y * y;
    float num = y * fmaf(z, fmaf(z, 21.0f, 1260.0f), 10395.0f);
    float den = fmaf(z, fmaf(z, fmaf(z, 1.0f, 210.0f), 4725.0f), 10395.0f);
    return __fdividef(num, den);
}
__device__ __forceinline__ float satp(float x) {        // 1000*tanh(x/1000)
    float y = x * 0.001f;
    y = fminf(fmaxf(y, -3.0f), 3.0f);
    return 1000.0f * padeth(y);
}
__device__ __forceinline__ float tanh_tiny(float y) {   // |y| <= 0.01
    return y * fmaf(-0.33333334f, y * y, 1.0f);
}
__device__ __forceinline__ float tanh_big(float y) {
    float a = fabsf(y);
    float e = __expf(2.0f * a);
    float t = __fdividef(e - 1.0f, e + 1.0f);
    t = (a > 15.0f) ? 1.0f : t;
    return copysignf(t, y);
}
__device__ __forceinline__ float sigf(float x) {
    float e = __expf(0.56f * (6.0f - x));
    return __fdividef(5.0f, 1.0f + e);
}

// ---------------- transpose ----------------
__global__ void k_trans(const float* __restrict__ in, const float* __restrict__ nz) {
    int idx = blockIdx.x * blockDim.x + threadIdx.x;
    if (idx >= TB*HH*NN) return;
    int t = idx % TB;
    int k = (idx / TB) % HH;
    int n = idx / (TB * HH);
    int dst = (t*HH + k)*NN + n;
    g_tin[dst] = in[idx];
    g_tnz[dst] = nz[idx * 3];
}

// ---------------- precompute ----------------
__global__ void k_pre(const float* __restrict__ wbb, const float* __restrict__ sc,
                      const int* __restrict__ dist, const float* __restrict__ lm) {
    __shared__ double red[256];
    int tid = threadIdx.x;
    double acc = 0.0;
    for (int idx = tid; idx < NN*NN; idx += 256) {
        int i = idx / NN, j = idx % NN;
        float w1 = expf(wbb[idx])      * sc[idx];
        float w2 = expf(wbb[j*NN + i]) * sc[j*NN + i];
        float wl = log1pf(0.5f * (w1 + w2));
        g_wl[idx] = wl;
        acc += (double)wl * (double)wl;
    }
    red[tid] = acc; __syncthreads();
    for (int s = 128; s; s >>= 1) { if (tid < s) red[tid] += red[tid + s]; __syncthreads(); }
    float inv = (float)(1.0 / sqrt(red[0]));

    if (tid < NN) {
        int i = tid;
        float rs = 0.0f;
        int c0 = 0, cx = 0, c1 = 0, c2 = 0;
        for (int j = 0; j < NN; ++j) {
            float wn = g_wl[i*NN + j] * inv;
            rs += wn;
            int d = dist[j*NN + i] >> 1;    // trunc(dist/2.0)
            if (d == 0) {
                if (c0 < K0) { g_w0[i*K0 + c0] = wn; g_o0[i*K0 + c0] = j; c0++; }
                else if (cx < X0) { g_x0[i*X0 + cx] = make_uint2(__float_as_uint(wn), (unsigned)j); cx++; }
            } else if (d == 1) {
                if (c1 < K1) { g_e1[i*K1 + c1] = make_uint2(__float_as_uint(wn), (unsigned)j); c1++; }
            } else {
                g_p2[i*P2SLOT + c2] = make_uint2(__float_as_uint(wn), ((unsigned)d << 16) | (unsigned)j); c2++;
            }
        }
        for (; c0 < K0; ++c0) { g_w0[i*K0 + c0] = 0.0f; g_o0[i*K0 + c0] = 0; }
        for (; c2 < P2SLOT; ++c2) g_p2[i*P2SLOT + c2] = make_uint2(0u, (2u << 16));
        g_x0c[i] = cx; g_e1c[i] = c1; g_rowsum[i] = rs;
    }
    __syncthreads();
    if (tid < OUTD) {
        float s = 0.0f;
        for (int j = 0; j < NN; ++j) s += fabsf(lm[tid*NN + j]);
        float invs = 1.0f / s;
        for (int j = 0; j < NN; ++j) g_lm1[tid*NN + j] = lm[tid*NN + j] * invs;
    }
    __syncthreads();
    if (tid < NN) {
        float cs = 0.0f;
        for (int o = 0; o < OUTD; ++o) cs += g_lm1[o*NN + tid];
        cs *= (1.0f / OUTD);
        for (int o = 0; o < OUTD; ++o) g_lmt[o*NN + tid] = g_lm1[o*NN + tid] - cs;
    }
}

// ---------------- main: 8-CTA cluster ----------------
__global__ __launch_bounds__(NTH, 1) __cluster_dims__(CLU, 1, 1)
void k_main(const float* __restrict__ hx, const float* __restrict__ hE,
            float* __restrict__ out)
{
    extern __shared__ float sm[];
    float* hist = sm;                 // [64][HP] hist ring (all CTAs keep a replica)
    float* MA   = hist + 64*HP;       // [208] live-M ping (rank0)
    float* MB   = MA + 208;           // [208] live-M pong (rank0)
    float* b2   = MB + 208;           // [2][208] D>=2 coupling (rank0; ranks write via DSMEM)
    float* emi  = b2 + 2*208;         // [2][208] E-I (rank1; rank0 writes via DSMEM)
    __shared__ __align__(8) unsigned long long s_mb[3];   // [0]=mbarB  [1]=mbarH0  [2]=mbarH1

    int tid = threadIdx.x;
    uint32_t rank = ctarank();
    uint32_t mbB  = smem_u32(&s_mb[0]);
    uint32_t mbH0 = smem_u32(&s_mb[1]);
    uint32_t mbH1 = smem_u32(&s_mb[2]);

    // ---- init: zero hist, prehistory, mbars ----
    for (int s = tid; s < 64*HP; s += NTH) hist[s] = 0.0f;
    __syncthreads();
    if (tid < NN) {
        for (int k = 1; k <= 49; ++k)
            hist[((0 - k) & 63)*HP + tid] = hE[tid*500 + k];   // Mf(-k) = hE[:,k]
        if (rank == 0) MA[tid] = hE[tid*500];                   // hEb[:,0]
    }
    if (tid == 0) {
        mbar_init(mbB, 7);     // 7 gather ranks arrive per round
        mbar_init(mbH0, 1);
        mbar_init(mbH1, 1);
    }
    __syncthreads();
    CLUSTER_SYNC();

    if (rank == 0) {
        // ================= INTEGRATOR =================
        int n = tid;
        bool act = (n < NN);
        float M=0,E=0,I=0,Mv=0,Ev=0,Iv=0,rs=0;
        float w0[K0]; int o0[K0];
        int xc = 0, e1c = 0;
        if (act) {
            M  = hx[n*6+0]; E  = hx[n*6+1]; I  = hx[n*6+2];
            Mv = hx[n*6+3]; Ev = hx[n*6+4]; Iv = hx[n*6+5];
            rs = g_rowsum[n]; xc = g_x0c[n]; e1c = g_e1c[n];
            #pragma unroll
            for (int e = 0; e < K0; ++e) { w0[e] = g_w0[n*K0 + e]; o0[e] = g_o0[n*K0 + e]; }
        }
        // u/z register ring, 3-step prefetch depth (layout (t,k,n), coalesced)
        float uu[4] = {0,0,0,0}, zz[4] = {0,0,0,0};
        if (act) {
            #pragma unroll
            for (int i = 0; i < 3; ++i) { uu[i] = g_tin[i*NN + n]; zz[i] = g_tnz[i*NN + n]; }
        }
        int sstep = 0;

        for (int t = 0; t < TB; ++t) {
            mbar_wait_cl(mbB, (uint32_t)(t & 1));          // base2(t) delivered to b2[t&1]
            float base = 0.0f;
            if (act) {
                base = b2[(t & 1)*208 + n];
                int sl = ((t - 1) & 63)*HP;
                const uint2* e1 = g_e1 + n*K1;
                for (int e = 0; e < e1c; ++e) {
                    uint2 v = e1[e];
                    base = fmaf(__uint_as_float(v.x), hist[sl + (int)v.y], base);
                }
            }

            #pragma unroll 4
            for (int k = 0; k < HH; ++k) {
                const float* rd = (k & 1) ? MB : MA;
                float*       wr = (k & 1) ? MA : MB;
                if (act) {
                    int sp = sstep + k + 3;
                    sp = sp < TB*HH ? sp : TB*HH - 1;
                    uu[(k + 3) & 3] = g_tin[sp*NN + n];
                    zz[(k + 3) & 3] = g_tnz[sp*NN + n];

                    float mnew = satp(fmaf(1e-4f, Mv, M));
                    wr[n] = mnew;
                    float l0 = base, l1 = 0.0f, l2 = 0.0f, l3 = 0.0f;
                    #pragma unroll
                    for (int e = 0; e < K0; e += 4) {
                        l0 = fmaf(w0[e+0], rd[o0[e+0]], l0);
                        l1 = fmaf(w0[e+1], rd[o0[e+1]], l1);
                        l2 = fmaf(w0[e+2], rd[o0[e+2]], l2);
                        l3 = fmaf(w0[e+3], rd[o0[e+3]], l3);
                    }
                    float led = (l0 + l1) + (l2 + l3);
                    if (xc) {
                        const uint2* xp = g_x0 + n*X0;
                        for (int e = 0; e < xc; ++e) {
                            uint2 v = xp[e];
                            led = fmaf(__uint_as_float(v.x), rd[(int)v.y], led);
                        }
                    }
                    float u = uu[k & 3], z = zz[k & 3];
                    float rM  = sigf(E - I);
                    float sgM = sigf(135.01f * M);
                    float rI  = 33.76f * sigf(33.76f * M);
                    float rE  = fmaf(250.0f, z, fmaf(1000.01f, led - rs*E, 108.01f * sgM));
                    float sM  = 500.0f * tanh_tiny(rM * 0.002f);
                    float sI  = 500.0f * padeth(rI * 0.002f);
                    float sE  = 500.0f * tanh_big(rE * 0.002f);
                    float En  = satp(fmaf(1e-4f, Ev, E));
                    float In  = satp(fmaf(1e-4f, Iv, I));
                    float Mvn = satp(fmaf(1e-4f, fmaf(328.25f, sM,                fmaf(-202.0f, Mv, -10201.0f*M)), Mv));
                    float Evn = satp(fmaf(1e-4f, fmaf(328.25f, fmaf(5.5f, u, sE), fmaf(-202.0f, Ev, -10201.0f*E)), Ev));
                    float Ivn = satp(fmaf(1e-4f, fmaf(1122.0f, sI,                fmaf(-102.0f, Iv,  -2601.0f*I)), Iv));
                    M = mnew; E = En; I = In; Mv = Mvn; Ev = Evn; Iv = Ivn;
                }
                __syncthreads();
            }
            sstep += HH;

            // publish Mf(t) + emi(t) to peers, then signal
            if (act) {
                hist[(t & 63)*HP + n] = M;
                uint32_t ha = smem_u32(&hist[(t & 63)*HP + n]);
                #pragma unroll
                for (uint32_t rk = 1; rk < CLU; ++rk) st_rk_f32(ha, rk, M);
                st_rk_f32(smem_u32(&emi[(t & 1)*208 + n]), 1, E - I);
            }
            __syncthreads();
            if (tid == 0) {
                fence_cluster();
                uint32_t hm = (t & 1) ? mbH1 : mbH0;
                #pragma unroll
                for (uint32_t rk = 1; rk < CLU; ++rk) mbar_arrive_rk(hm, rk);
            }
        }
        if (act) {
            float* st = out + OUTD*TB + n*6;
            st[0] = M;  st[1] = E;  st[2] = I;
            st[3] = Mv; st[4] = Ev; st[5] = Iv;
        }
    } else {
        // ================= GATHER RANKS 1..7 =================
        int r0 = ((int)rank - 1) * 29;
        int r1 = r0 + 29; if (r1 > NN) r1 = NN;
        int w = tid >> 5, l = tid & 31;
        int c0 = 0, c1 = 0;   // wait counters per mbarH
        uint32_t b2loc0 = smem_u32(&b2[0]);

        for (int r = 0; r < TB; ++r) {
            if (r >= 2) {
                int a = r - 2;
                if (!(a & 1)) { mbar_wait_cl(mbH0, (uint32_t)(c0 & 1)); c0++; }
                else          { mbar_wait_cl(mbH1, (uint32_t)(c1 & 1)); c1++; }
            }
            // rank1: eeg for step r-2 (emi already delivered with that arrival)
            if (rank == 1 && r >= 2 && tid < 2*OUTD) {
                int rr = r - 2;
                int o = tid >> 1, half = tid & 1;
                const float* lr = g_lmt + o*NN + half*100;
                const float* er = emi + (rr & 1)*208 + half*100;
                float s = 0.0f;
                #pragma unroll 10
                for (int j = 0; j < 100; ++j) s = fmaf(lr[j], er[j], s);
                s += __shfl_xor_sync(0xffffffffu, s, 1);
                if (!half) out[o*TB + rr] = fmaf(5.0f, s, -2.0f);
            }
            // D>=2 coupling for step r, rows [r0,r1), warp-per-row
            for (int row = r0 + w; row < r1; row += 7) {
                const uint2* pp = g_p2 + row*P2SLOT;
                float a = 0.0f;
                #pragma unroll
                for (int e = 0; e < 7; ++e) {
                    uint2 v = pp[e*32 + l];
                    int j = v.y & 0xffff, D = v.y >> 16;
                    a = fmaf(__uint_as_float(v.x), hist[((r - D) & 63)*HP + j], a);
                }
                #pragma unroll
                for (int o = 16; o; o >>= 1) a += __shfl_down_sync(0xffffffffu, a, o);
                if (!l) st_rk_f32(b2loc0 + ((r & 1)*208 + row)*4, 0, a);
            }
            __syncthreads();
            if (tid == 0) { fence_cluster(); mbar_arrive_rk(mbB, 0); }
        }
        // rank1 tail: eeg(398), eeg(399)
        if (rank == 1) {
            mbar_wait_cl(mbH0, (uint32_t)(c0 & 1)); c0++;     // Mf/emi(398)
            if (tid < 2*OUTD) {
                int rr = TB - 2;
                int o = tid >> 1, half = tid & 1;
                const float* lr = g_lmt + o*NN + half*100;
                const float* er = emi + (rr & 1)*208 + half*100;
                float s = 0.0f;
                #pragma unroll 10
                for (int j = 0; j < 100; ++j) s = fmaf(lr[j], er[j], s);
                s += __shfl_xor_sync(0xffffffffu, s, 1);
                if (!half) out[o*TB + rr] = fmaf(5.0f, s, -2.0f);
            }
            mbar_wait_cl(mbH1, (uint32_t)(c1 & 1)); c1++;     // Mf/emi(399)
            if (tid < 2*OUTD) {
                int rr = TB - 1;
                int o = tid >> 1, half = tid & 1;
                const float* lr = g_lmt + o*NN + half*100;
                const float* er = emi + (rr & 1)*208 + half*100;
                float s = 0.0f;
                #pragma unroll 10
                for (int j = 0; j < 100; ++j) s = fmaf(lr[j], er[j], s);
                s += __shfl_xor_sync(0xffffffffu, s, 1);
                if (!half) out[o*TB + rr] = fmaf(5.0f, s, -2.0f);
            }
        }
    }
    CLUSTER_SYNC();
}

// ---------------- harness entry ----------------
extern "C" void kernel_launch(void* const* d_in, const int* in_sizes, int n_in,
                              void* d_out, int out_size) {
    const float* input    = (const float*)d_in[0];
    const float* noise_in = (const float*)d_in[1];
    const float* hx       = (const float*)d_in[3];
    const float* hE       = (const float*)d_in[4];
    const float* wbb      = (const float*)d_in[5];
    const float* lm       = (const float*)d_in[6];
    const float* sc       = (const float*)d_in[7];
    const int*   dist     = (const int*)d_in[8];
    float*       out      = (float*)d_out;

    cudaFuncSetAttribute(k_main, cudaFuncAttributeMaxDynamicSharedMemorySize, SMEM_BYTES);

    k_trans<<<(TB*HH*NN + 255)/256, 256>>>(input, noise_in);
    k_pre  <<<1, 256>>>(wbb, sc, dist, lm);
    k_main <<<CLU, NTH, SMEM_BYTES>>>(hx, hE, out);
}

// round 5
// speedup vs baseline: 3.8590x; 1.0080x over previous
#include <cuda_runtime.h>
#include <stdint.h>

#define NN    200
#define HH    20
#define TB    400
#define OUTD  64
#define HP    201
#define NTH   224
#define K0    12         // unrolled zero-delay CSR slots
#define X0    32         // zero-delay spill capacity (global, rare)
#define K1    48         // delay==1 capacity
#define P2SLOT 224       // padded D>=2 entries per row (7 per lane)
#define CLU   8

// smem: hist 64*201 + MA 208 + MB 208 + b2 2*208 + emi 2*208
#define SMEM_FLOATS (64*HP + 208 + 208 + 2*208 + 2*208)
#define SMEM_BYTES  (SMEM_FLOATS * 4)

// ---------------- device scratch ----------------
__device__ __align__(16) float g_tin[TB*HH*NN];   // (t,k,n)
__device__ __align__(16) float g_tnz[TB*HH*NN];   // (t,k,n)
__device__ float g_wl [NN*NN];
__device__ float g_w0 [NN*K0];
__device__ int   g_o0 [NN*K0];
__device__ uint2 g_x0 [NN*X0];    __device__ int g_x0c[NN];
__device__ uint2 g_e1 [NN*K1];    __device__ int g_e1c[NN];
__device__ uint2 g_p2 [NN*P2SLOT];
__device__ float g_rowsum[NN];
__device__ float g_lm1[OUTD*NN];
__device__ float g_lmt[OUTD*NN];

// ---------------- cluster / mbarrier helpers ----------------
__device__ __forceinline__ uint32_t smem_u32(const void* p) {
    uint32_t a;
    asm("{ .reg .u64 t; cvta.to.shared.u64 t, %1; cvt.u32.u64 %0, t; }" : "=r"(a) : "l"(p));
    return a;
}
__device__ __forceinline__ uint32_t ctarank() {
    uint32_t r; asm("mov.u32 %0, %%cluster_ctarank;" : "=r"(r)); return r;
}
__device__ __forceinline__ void mbar_init(uint32_t a, uint32_t cnt) {
    asm volatile("mbarrier.init.shared.b64 [%0], %1;" :: "r"(a), "r"(cnt) : "memory");
}
__device__ __forceinline__ void fence_cluster() {
    asm volatile("fence.acq_rel.cluster;" ::: "memory");
}
__device__ __forceinline__ void mbar_wait_cl(uint32_t mbar, uint32_t parity) {
    asm volatile(
        "{\n\t.reg .pred P;\n"
        "W%=:\n\t"
        "mbarrier.try_wait.parity.acquire.cluster.shared::cta.b64 P, [%0], %1, 0x989680;\n\t"
        "@P bra.uni D%=;\n\t"
        "bra.uni W%=;\n"
        "D%=:\n\t}"
        :: "r"(mbar), "r"(parity) : "memory");
}
__device__ __forceinline__ void mbar_arrive_rk(uint32_t mbar_local, uint32_t rk) {
    uint32_t rem;
    asm volatile("mapa.shared::cluster.u32 %0, %1, %2;" : "=r"(rem) : "r"(mbar_local), "r"(rk));
    asm volatile("mbarrier.arrive.release.cluster.shared::cluster.b64 _, [%0];" :: "r"(rem) : "memory");
}
__device__ __forceinline__ void st_rk_f32(uint32_t local, uint32_t rk, float v) {
    uint32_t rem;
    asm volatile("mapa.shared::cluster.u32 %0, %1, %2;" : "=r"(rem) : "r"(local), "r"(rk));
    asm volatile("st.shared::cluster.f32 [%0], %1;" :: "r"(rem), "f"(v) : "memory");
}
#define CLUSTER_SYNC() do { \
    asm volatile("barrier.cluster.arrive.aligned;" ::: "memory"); \
    asm volatile("barrier.cluster.wait.aligned;"  ::: "memory"); \
} while (0)

// ---------------- math helpers (identical to validated R3) ----------------
__device__ __forceinline__ float padeth(float y) {     // tanh, |y|<=3
    float z = y * y;
    float num = y * fmaf(z, fmaf(z, 21.0f, 1260.0f), 10395.0f);
    float den = fmaf(z, fmaf(z, fmaf(z, 1.0f, 210.0f), 4725.0f), 10395.0f);
    return __fdividef(num, den);
}
__device__ __forceinline__ float satp(float x) {        // 1000*tanh(x/1000)
    float y = x * 0.001f;
    y = fminf(fmaxf(y, -3.0f), 3.0f);
    return 1000.0f * padeth(y);
}
__device__ __forceinline__ float tanh_tiny(float y) {   // |y| <= 0.01
    return y * fmaf(-0.33333334f, y * y, 1.0f);
}
__device__ __forceinline__ float tanh_big(float y) {
    float a = fabsf(y);
    float e = __expf(2.0f * a);
    float t = __fdividef(e - 1.0f, e + 1.0f);
    t = (a > 15.0f) ? 1.0f : t;
    return copysignf(t, y);
}
__device__ __forceinline__ float sigf(float x) {
    float e = __expf(0.56f * (6.0f - x));
    return __fdividef(5.0f, 1.0f + e);
}

// ---------------- transpose ----------------
__global__ void k_trans(const float* __restrict__ in, const float* __restrict__ nz) {
    int idx = blockIdx.x * blockDim.x + threadIdx.x;
    if (idx >= TB*HH*NN) return;
    int t = idx % TB;
    int k = (idx / TB) % HH;
    int n = idx / (TB * HH);
    int dst = (t*HH + k)*NN + n;
    g_tin[dst] = in[idx];
    g_tnz[dst] = nz[idx * 3];
}

// ---------------- precompute ----------------
__global__ void k_pre(const float* __restrict__ wbb, const float* __restrict__ sc,
                      const int* __restrict__ dist, const float* __restrict__ lm) {
    __shared__ double red[256];
    int tid = threadIdx.x;
    double acc = 0.0;
    for (int idx = tid; idx < NN*NN; idx += 256) {
        int i = idx / NN, j = idx % NN;
        float w1 = expf(wbb[idx])      * sc[idx];
        float w2 = expf(wbb[j*NN + i]) * sc[j*NN + i];
        float wl = log1pf(0.5f * (w1 + w2));
        g_wl[idx] = wl;
        acc += (double)wl * (double)wl;
    }
    red[tid] = acc; __syncthreads();
    for (int s = 128; s; s >>= 1) { if (tid < s) red[tid] += red[tid + s]; __syncthreads(); }
    float inv = (float)(1.0 / sqrt(red[0]));

    if (tid < NN) {
        int i = tid;
        float rs = 0.0f;
        int c0 = 0, cx = 0, c1 = 0, c2 = 0;
        for (int j = 0; j < NN; ++j) {
            float wn = g_wl[i*NN + j] * inv;
            rs += wn;
            int d = dist[j*NN + i] >> 1;    // trunc(dist/2.0)
            if (d == 0) {
                if (c0 < K0) { g_w0[i*K0 + c0] = wn; g_o0[i*K0 + c0] = j; c0++; }
                else if (cx < X0) { g_x0[i*X0 + cx] = make_uint2(__float_as_uint(wn), (unsigned)j); cx++; }
            } else if (d == 1) {
                if (c1 < K1) { g_e1[i*K1 + c1] = make_uint2(__float_as_uint(wn), (unsigned)j); c1++; }
            } else {
                g_p2[i*P2SLOT + c2] = make_uint2(__float_as_uint(wn), ((unsigned)d << 16) | (unsigned)j); c2++;
            }
        }
        for (; c0 < K0; ++c0) { g_w0[i*K0 + c0] = 0.0f; g_o0[i*K0 + c0] = 0; }
        for (; c2 < P2SLOT; ++c2) g_p2[i*P2SLOT + c2] = make_uint2(0u, (2u << 16));
        g_x0c[i] = cx; g_e1c[i] = c1; g_rowsum[i] = rs;
    }
    __syncthreads();
    if (tid < OUTD) {
        float s = 0.0f;
        for (int j = 0; j < NN; ++j) s += fabsf(lm[tid*NN + j]);
        float invs = 1.0f / s;
        for (int j = 0; j < NN; ++j) g_lm1[tid*NN + j] = lm[tid*NN + j] * invs;
    }
    __syncthreads();
    if (tid < NN) {
        float cs = 0.0f;
        for (int o = 0; o < OUTD; ++o) cs += g_lm1[o*NN + tid];
        cs *= (1.0f / OUTD);
        for (int o = 0; o < OUTD; ++o) g_lmt[o*NN + tid] = g_lm1[o*NN + tid] - cs;
    }
}

// ---------------- main: 8-CTA cluster ----------------
__global__ __launch_bounds__(NTH, 1) __cluster_dims__(CLU, 1, 1)
void k_main(const float* __restrict__ hx, const float* __restrict__ hE,
            float* __restrict__ out)
{
    extern __shared__ float sm[];
    float* hist = sm;                 // [64][HP] hist ring (all CTAs keep a replica)
    float* MA   = hist + 64*HP;       // [208] live-M ping (rank0)
    float* MB   = MA + 208;           // [208] live-M pong (rank0)
    float* b2   = MB + 208;           // [2][208] D>=2 coupling (rank0; ranks write via DSMEM)
    float* emi  = b2 + 2*208;         // [2][208] E-I (rank1; rank0 writes via DSMEM)
    __shared__ __align__(8) unsigned long long s_mb[3];   // [0]=mbarB  [1]=mbarH0  [2]=mbarH1

    int tid = threadIdx.x;
    uint32_t rank = ctarank();
    uint32_t mbB  = smem_u32(&s_mb[0]);
    uint32_t mbH0 = smem_u32(&s_mb[1]);
    uint32_t mbH1 = smem_u32(&s_mb[2]);

    // ---- init: zero hist, prehistory, mbars ----
    for (int s = tid; s < 64*HP; s += NTH) hist[s] = 0.0f;
    __syncthreads();
    if (tid < NN) {
        for (int k = 1; k <= 49; ++k)
            hist[((0 - k) & 63)*HP + tid] = hE[tid*500 + k];   // Mf(-k) = hE[:,k]
        if (rank == 0) MA[tid] = hE[tid*500];                   // hEb[:,0]
    }
    if (tid == 0) {
        mbar_init(mbB, 7);     // 7 gather ranks arrive per round
        mbar_init(mbH0, 1);
        mbar_init(mbH1, 1);
    }
    __syncthreads();
    CLUSTER_SYNC();

    if (rank == 0) {
        // ================= INTEGRATOR =================
        int n = tid;
        bool act = (n < NN);
        float M=0,E=0,I=0,Mv=0,Ev=0,Iv=0,rs=0;
        float w0[K0]; int o0[K0];
        int xc = 0, e1c = 0;
        if (act) {
            M  = hx[n*6+0]; E  = hx[n*6+1]; I  = hx[n*6+2];
            Mv = hx[n*6+3]; Ev = hx[n*6+4]; Iv = hx[n*6+5];
            rs = g_rowsum[n]; xc = g_x0c[n]; e1c = g_e1c[n];
            #pragma unroll
            for (int e = 0; e < K0; ++e) { w0[e] = g_w0[n*K0 + e]; o0[e] = g_o0[n*K0 + e]; }
        }
        // u/z register ring, 3-step prefetch depth (layout (t,k,n), coalesced)
        float uu[4] = {0,0,0,0}, zz[4] = {0,0,0,0};
        if (act) {
            #pragma unroll
            for (int i = 0; i < 3; ++i) { uu[i] = g_tin[i*NN + n]; zz[i] = g_tnz[i*NN + n]; }
        }
        int sstep = 0;

        for (int t = 0; t < TB; ++t) {
            mbar_wait_cl(mbB, (uint32_t)(t & 1));          // base2(t) delivered to b2[t&1]
            float base = 0.0f;
            if (act) {
                base = b2[(t & 1)*208 + n];
                int sl = ((t - 1) & 63)*HP;
                const uint2* e1 = g_e1 + n*K1;
                for (int e = 0; e < e1c; ++e) {
                    uint2 v = e1[e];
                    base = fmaf(__uint_as_float(v.x), hist[sl + (int)v.y], base);
                }
            }

            #pragma unroll 4
            for (int k = 0; k < HH; ++k) {
                const float* rd = (k & 1) ? MB : MA;
                float*       wr = (k & 1) ? MA : MB;
                if (act) {
                    int sp = sstep + k + 3;
                    sp = sp < TB*HH ? sp : TB*HH - 1;
                    uu[(k + 3) & 3] = g_tin[sp*NN + n];
                    zz[(k + 3) & 3] = g_tnz[sp*NN + n];

                    float mnew = satp(fmaf(1e-4f, Mv, M));
                    wr[n] = mnew;
                    float l0 = base, l1 = 0.0f, l2 = 0.0f, l3 = 0.0f;
                    #pragma unroll
                    for (int e = 0; e < K0; e += 4) {
                        l0 = fmaf(w0[e+0], rd[o0[e+0]], l0);
                        l1 = fmaf(w0[e+1], rd[o0[e+1]], l1);
                        l2 = fmaf(w0[e+2], rd[o0[e+2]], l2);
                        l3 = fmaf(w0[e+3], rd[o0[e+3]], l3);
                    }
                    float led = (l0 + l1) + (l2 + l3);
                    if (xc) {
                        const uint2* xp = g_x0 + n*X0;
                        for (int e = 0; e < xc; ++e) {
                            uint2 v = xp[e];
                            led = fmaf(__uint_as_float(v.x), rd[(int)v.y], led);
                        }
                    }
                    float u = uu[k & 3], z = zz[k & 3];
                    float rM  = sigf(E - I);
                    float sgM = sigf(135.01f * M);
                    float rI  = 33.76f * sigf(33.76f * M);
                    float rE  = fmaf(250.0f, z, fmaf(1000.01f, led - rs*E, 108.01f * sgM));
                    float sM  = 500.0f * tanh_tiny(rM * 0.002f);
                    float sI  = 500.0f * padeth(rI * 0.002f);
                    float sE  = 500.0f * tanh_big(rE * 0.002f);
                    float En  = satp(fmaf(1e-4f, Ev, E));
                    float In  = satp(fmaf(1e-4f, Iv, I));
                    float Mvn = satp(fmaf(1e-4f, fmaf(328.25f, sM,                fmaf(-202.0f, Mv, -10201.0f*M)), Mv));
                    float Evn = satp(fmaf(1e-4f, fmaf(328.25f, fmaf(5.5f, u, sE), fmaf(-202.0f, Ev, -10201.0f*E)), Ev));
                    float Ivn = satp(fmaf(1e-4f, fmaf(1122.0f, sI,                fmaf(-102.0f, Iv,  -2601.0f*I)), Iv));
                    M = mnew; E = En; I = In; Mv = Mvn; Ev = Evn; Iv = Ivn;
                }
                __syncthreads();
            }
            sstep += HH;

            // publish Mf(t) + emi(t) to peers, then signal
            if (act) {
                hist[(t & 63)*HP + n] = M;
                uint32_t ha = smem_u32(&hist[(t & 63)*HP + n]);
                #pragma unroll
                for (uint32_t rk = 1; rk < CLU; ++rk) st_rk_f32(ha, rk, M);
                st_rk_f32(smem_u32(&emi[(t & 1)*208 + n]), 1, E - I);
            }
            __syncthreads();
            if (tid == 0) {
                fence_cluster();
                uint32_t hm = (t & 1) ? mbH1 : mbH0;
                #pragma unroll
                for (uint32_t rk = 1; rk < CLU; ++rk) mbar_arrive_rk(hm, rk);
            }
        }
        if (act) {
            float* st = out + OUTD*TB + n*6;
            st[0] = M;  st[1] = E;  st[2] = I;
            st[3] = Mv; st[4] = Ev; st[5] = Iv;
        }
    } else {
        // ================= GATHER RANKS 1..7 =================
        int r0 = ((int)rank - 1) * 29;
        int r1 = r0 + 29; if (r1 > NN) r1 = NN;
        int w = tid >> 5, l = tid & 31;
        int c0 = 0, c1 = 0;   // wait counters per mbarH
        uint32_t b2loc0 = smem_u32(&b2[0]);

        for (int r = 0; r < TB; ++r) {
            if (r >= 2) {
                int a = r - 2;
                if (!(a & 1)) { mbar_wait_cl(mbH0, (uint32_t)(c0 & 1)); c0++; }
                else          { mbar_wait_cl(mbH1, (uint32_t)(c1 & 1)); c1++; }
            }
            // rank1: eeg for step r-2 (emi already delivered with that arrival)
            if (rank == 1 && r >= 2 && tid < 2*OUTD) {
                int rr = r - 2;
                int o = tid >> 1, half = tid & 1;
                const float* lr = g_lmt + o*NN + half*100;
                const float* er = emi + (rr & 1)*208 + half*100;
                float s = 0.0f;
                #pragma unroll 10
                for (int j = 0; j < 100; ++j) s = fmaf(lr[j], er[j], s);
                s += __shfl_xor_sync(0xffffffffu, s, 1);
                if (!half) out[o*TB + rr] = fmaf(5.0f, s, -2.0f);
            }
            // D>=2 coupling for step r, rows [r0,r1), warp-per-row
            for (int row = r0 + w; row < r1; row += 7) {
                const uint2* pp = g_p2 + row*P2SLOT;
                float a = 0.0f;
                #pragma unroll
                for (int e = 0; e < 7; ++e) {
                    uint2 v = pp[e*32 + l];
                    int j = v.y & 0xffff, D = v.y >> 16;
                    a = fmaf(__uint_as_float(v.x), hist[((r - D) & 63)*HP + j], a);
                }
                #pragma unroll
                for (int o = 16; o; o >>= 1) a += __shfl_down_sync(0xffffffffu, a, o);
                if (!l) st_rk_f32(b2loc0 + ((r & 1)*208 + row)*4, 0, a);
            }
            __syncthreads();
            if (tid == 0) { fence_cluster(); mbar_arrive_rk(mbB, 0); }
        }
        // rank1 tail: eeg(398), eeg(399)
        if (rank == 1) {
            mbar_wait_cl(mbH0, (uint32_t)(c0 & 1)); c0++;     // Mf/emi(398)
            if (tid < 2*OUTD) {
                int rr = TB - 2;
                int o = tid >> 1, half = tid & 1;
                const float* lr = g_lmt + o*NN + half*100;
                const float* er = emi + (rr & 1)*208 + half*100;
                float s = 0.0f;
                #pragma unroll 10
                for (int j = 0; j < 100; ++j) s = fmaf(lr[j], er[j], s);
                s += __shfl_xor_sync(0xffffffffu, s, 1);
                if (!half) out[o*TB + rr] = fmaf(5.0f, s, -2.0f);
            }
            mbar_wait_cl(mbH1, (uint32_t)(c1 & 1)); c1++;     // Mf/emi(399)
            if (tid < 2*OUTD) {
                int rr = TB - 1;
                int o = tid >> 1, half = tid & 1;
                const float* lr = g_lmt + o*NN + half*100;
                const float* er = emi + (rr & 1)*208 + half*100;
                float s = 0.0f;
                #pragma unroll 10
                for (int j = 0; j < 100; ++j) s = fmaf(lr[j], er[j], s);
                s += __shfl_xor_sync(0xffffffffu, s, 1);
                if (!half) out[o*TB + rr] = fmaf(5.0f, s, -2.0f);
            }
        }
    }
    CLUSTER_SYNC();
}

// ---------------- harness entry ----------------
extern "C" void kernel_launch(void* const* d_in, const int* in_sizes, int n_in,
                              void* d_out, int out_size) {
    const float* input    = (const float*)d_in[0];
    const float* noise_in = (const float*)d_in[1];
    const float* hx       = (const float*)d_in[3];
    const float* hE       = (const float*)d_in[4];
    const float* wbb      = (const float*)d_in[5];
    const float* lm       = (const float*)d_in[6];
    const float* sc       = (const float*)d_in[7];
    const int*   dist     = (const int*)d_in[8];
    float*       out      = (float*)d_out;

    cudaFuncSetAttribute(k_main, cudaFuncAttributeMaxDynamicSharedMemorySize, SMEM_BYTES);

    k_trans<<<(TB*HH*NN + 255)/256, 256>>>(input, noise_in);
    k_pre  <<<1, 256>>>(wbb, sc, dist, lm);
    k_main <<<CLU, NTH, SMEM_BYTES>>>(hx, hE, out);
}